// round 5
// baseline (speedup 1.0000x reference)
#include <cuda_runtime.h>
#include <mma.h>
#include <cstdint>

using namespace nvcuda;

#define B_ 64
#define C_ 256
#define P_ 196
#define A_ 512
#define D_ 512
#define E_ 512
#define V_ 30000
#define T_ 20
#define G_ 2048   // 4*D

// ---------------- scratch (device globals; no allocation allowed) ----------------
__device__ __align__(128) float g_feats[B_*P_*C_];    // [b][p][c]
__device__ __align__(128) float g_encatt[B_*P_*A_];   // [b][p][a]
__device__ __align__(128) float g_h[B_*D_];
__device__ __align__(128) float g_c[B_*D_];
__device__ __align__(128) float g_ctx[B_*C_];
__device__ __align__(128) float g_gpart[5*B_*G_];     // K-split partial gate sums
__device__ __align__(128) float g_H[T_*B_*D_];        // [t][b][d]

// ---------------- init h0 = c0 = 0 ----------------
__global__ void __launch_bounds__(256) k_init() {
    int i = blockIdx.x * blockDim.x + threadIdx.x;
    if (i < B_ * D_) { g_h[i] = 0.f; g_c[i] = 0.f; }
}

// ---------------- feats[b][p][c] = enc[b][c][p] ----------------
__global__ void __launch_bounds__(256) k_transpose(const float* __restrict__ enc) {
    __shared__ float tile[32][33];
    int b = blockIdx.z, c0 = blockIdx.y * 32, p0 = blockIdx.x * 32;
    int tx = threadIdx.x, ty = threadIdx.y;
#pragma unroll
    for (int i = 0; i < 4; i++) {
        int c = c0 + ty + i * 8, p = p0 + tx;
        if (p < P_) tile[ty + i * 8][tx] = enc[(b * C_ + c) * P_ + p];
    }
    __syncthreads();
#pragma unroll
    for (int i = 0; i < 4; i++) {
        int p = p0 + ty + i * 8, c = c0 + tx;
        if (p < P_) g_feats[(b * P_ + p) * C_ + c] = tile[tx][ty + i * 8];
    }
}

// ---------------- tf32 WMMA GEMM: C[M,N] = A[M,K] @ B[K,N] + bias[N] ----------------
// 64x64 block tile, 4 warps (2x2), each warp 32x32 (2x2 m16n16k8 frags), BK=32.
// MODE 0: A = g_feats, C = g_encatt (enc_att precompute, K=256, N=512)
// MODE 1: A = g_H, C = out with remap row r=t*64+b -> out[(b*T+t)*N+n] (final fc)
template<int MODE>
__global__ void __launch_bounds__(128, 2) k_gemm_tf32(const float* __restrict__ Bm,
                            const float* __restrict__ bias,
                            float* __restrict__ Cout,
                            int M, int N, int K) {
    __shared__ float As[64][40];
    __shared__ float Bs[32][72];
    __shared__ float Cs[64][72];
    const float* Aa = (MODE == 0) ? g_feats : g_H;
    int m0 = blockIdx.x * 64, n0 = blockIdx.y * 64;
    int tid = threadIdx.x;
    int warp = tid >> 5;
    int wm = warp >> 1, wn = warp & 1;

    wmma::fragment<wmma::accumulator, 16, 16, 8, float> acc[2][2];
#pragma unroll
    for (int i = 0; i < 2; i++)
#pragma unroll
        for (int j = 0; j < 2; j++) wmma::fill_fragment(acc[i][j], 0.f);

    for (int k0 = 0; k0 < K; k0 += 32) {
#pragma unroll
        for (int i = 0; i < 4; i++) {           // stage A 64x32
            int idx = tid + i * 128;
            int r = idx >> 3, c4 = (idx & 7) * 4;
            float4 v = *(const float4*)&Aa[(size_t)(m0 + r) * K + k0 + c4];
            *(float4*)&As[r][c4] = v;
        }
#pragma unroll
        for (int i = 0; i < 4; i++) {           // stage B 32x64 (bounds on n)
            int idx = tid + i * 128;
            int kk = idx >> 4, c4 = (idx & 15) * 4;
            int n = n0 + c4;
            float4 v = make_float4(0.f, 0.f, 0.f, 0.f);
            if (n < N) v = *(const float4*)&Bm[(size_t)(k0 + kk) * N + n];
            *(float4*)&Bs[kk][c4] = v;
        }
        __syncthreads();
#pragma unroll
        for (int kk = 0; kk < 32; kk += 8) {
            wmma::fragment<wmma::matrix_a, 16, 16, 8, wmma::precision::tf32, wmma::row_major> a0, a1;
            wmma::fragment<wmma::matrix_b, 16, 16, 8, wmma::precision::tf32, wmma::row_major> b0, b1;
            wmma::load_matrix_sync(a0, &As[wm * 32][kk], 40);
            wmma::load_matrix_sync(a1, &As[wm * 32 + 16][kk], 40);
            wmma::load_matrix_sync(b0, &Bs[kk][wn * 32], 72);
            wmma::load_matrix_sync(b1, &Bs[kk][wn * 32 + 16], 72);
#pragma unroll
            for (int e = 0; e < a0.num_elements; e++) {
                a0.x[e] = wmma::__float_to_tf32(a0.x[e]);
                a1.x[e] = wmma::__float_to_tf32(a1.x[e]);
            }
#pragma unroll
            for (int e = 0; e < b0.num_elements; e++) {
                b0.x[e] = wmma::__float_to_tf32(b0.x[e]);
                b1.x[e] = wmma::__float_to_tf32(b1.x[e]);
            }
            wmma::mma_sync(acc[0][0], a0, b0, acc[0][0]);
            wmma::mma_sync(acc[0][1], a0, b1, acc[0][1]);
            wmma::mma_sync(acc[1][0], a1, b0, acc[1][0]);
            wmma::mma_sync(acc[1][1], a1, b1, acc[1][1]);
        }
        __syncthreads();
    }
#pragma unroll
    for (int i = 0; i < 2; i++)
#pragma unroll
        for (int j = 0; j < 2; j++)
            wmma::store_matrix_sync(&Cs[wm * 32 + i * 16][wn * 32 + j * 16], acc[i][j], 72,
                                    wmma::mem_row_major);
    __syncthreads();
    float* Cdst = (MODE == 0) ? g_encatt : Cout;
    for (int idx = tid; idx < 64 * 64; idx += 128) {
        int rr = idx >> 6, cc = idx & 63;
        int n = n0 + cc;
        if (n >= N) continue;
        int row = m0 + rr;
        float val = Cs[rr][cc] + bias[n];
        if (MODE == 1) {
            int b = row & 63, t = row >> 6;
            Cdst[(size_t)(b * T_ + t) * N + n] = val;
        } else {
            Cdst[(size_t)row * N + n] = val;
        }
    }
}

// ---------------- fused attention: dec_att + logits + softmax + context ----------------
// one block per batch element b, 256 threads
__global__ void __launch_bounds__(256) k_attention(const float* __restrict__ Wd,
                                                   const float* __restrict__ bd,
                                                   const float* __restrict__ Wf) {
    int b = blockIdx.x;
    int tid = threadIdx.x;
    int lane = tid & 31, warp = tid >> 5;
    __shared__ float sh[512], sdec[512], swf[512], slog[224], sred[8];
    for (int i = tid; i < 512; i += 256) { sh[i] = g_h[b * 512 + i]; swf[i] = Wf[i]; }
    __syncthreads();
    // dec_att[a] = sum_k h[k] * Wd[k][a] + bd[a]   (2 outputs per thread, coalesced over a)
    {
        float acc0 = bd[tid], acc1 = bd[tid + 256];
        const float* w0 = Wd + tid;
        const float* w1 = Wd + tid + 256;
#pragma unroll 8
        for (int k = 0; k < 512; k++) {
            float hv = sh[k];
            acc0 = fmaf(hv, w0[(size_t)k * 512], acc0);
            acc1 = fmaf(hv, w1[(size_t)k * 512], acc1);
        }
        sdec[tid] = acc0; sdec[tid + 256] = acc1;
    }
    __syncthreads();
    // logits[p] = sum_k relu(encatt[b][p][k] + dec[k]) * Wf[k]
    for (int p = warp; p < P_; p += 8) {
        const float* row = &g_encatt[((size_t)b * P_ + p) * A_];
        float acc = 0.f;
#pragma unroll
        for (int j = 0; j < 4; j++) {
            int k = (lane + j * 32) * 4;
            float4 e = *(const float4*)&row[k];
            float4 dd = *(const float4*)&sdec[k];
            float4 w = *(const float4*)&swf[k];
            acc += fmaxf(e.x + dd.x, 0.f) * w.x + fmaxf(e.y + dd.y, 0.f) * w.y
                 + fmaxf(e.z + dd.z, 0.f) * w.z + fmaxf(e.w + dd.w, 0.f) * w.w;
        }
#pragma unroll
        for (int o = 16; o > 0; o >>= 1) acc += __shfl_down_sync(0xffffffff, acc, o);
        if (lane == 0) slog[p] = acc;
    }
    __syncthreads();
    // softmax max
    float m = -1e30f;
    for (int p = tid; p < P_; p += 256) m = fmaxf(m, slog[p]);
#pragma unroll
    for (int o = 16; o > 0; o >>= 1) m = fmaxf(m, __shfl_xor_sync(0xffffffff, m, o));
    if (lane == 0) sred[warp] = m;
    __syncthreads();
    float gm = fmaxf(fmaxf(fmaxf(sred[0], sred[1]), fmaxf(sred[2], sred[3])),
                     fmaxf(fmaxf(sred[4], sred[5]), fmaxf(sred[6], sred[7])));
    __syncthreads();
    // exp + sum
    float s = 0.f;
    for (int p = tid; p < P_; p += 256) { float e = expf(slog[p] - gm); slog[p] = e; s += e; }
#pragma unroll
    for (int o = 16; o > 0; o >>= 1) s += __shfl_xor_sync(0xffffffff, s, o);
    if (lane == 0) sred[warp] = s;
    __syncthreads();
    float tot = sred[0] + sred[1] + sred[2] + sred[3] + sred[4] + sred[5] + sred[6] + sred[7];
    float inv = 1.f / tot;
    __syncthreads();
    // context[c] = sum_p alpha[p] * feats[b][p][c]   (thread = c, coalesced over c)
    float accv = 0.f;
    const float* fb = &g_feats[(size_t)b * P_ * C_];
#pragma unroll 4
    for (int p = 0; p < P_; p++) accv += slog[p] * fb[p * C_ + tid];
    g_ctx[b * C_ + tid] = accv * inv;
}

// ---------------- gates partial GEMM: K split into 5 chunks of 256 ----------------
// x~[b][k] = [ emb(512) | ctx(256) | h(512) ],  W~[n][k] = [ W_ih(768) | W_hh(512) ]
// captions are int32 (JAX default x64-disabled downcasts jnp.int64 -> int32)
__global__ void __launch_bounds__(256) k_gates(const int* __restrict__ cap,
                        const float* __restrict__ emb,
                        const float* __restrict__ Wih,
                        const float* __restrict__ Whh,
                        int t) {
    __shared__ float As[16][68];    // [k][m]
    __shared__ float Bs[16][132];   // [k][n]
    int n0 = blockIdx.x * 128;
    int z = blockIdx.y;             // K chunk 0..4
    int tid = threadIdx.x;
    int tx = tid & 15, ty = tid >> 4;

    int ms = tid >> 2, kq = (tid & 3) * 4;
    const float* arow;
    if (z < 2) { int ci = cap[ms * T_ + t]; arow = emb + (size_t)ci * E_ + z * 256; }
    else if (z == 2) arow = g_ctx + ms * C_;
    else arow = g_h + ms * D_ + (z - 3) * 256;
    const float* Wb; int ldw;
    if (z < 3) { Wb = Wih + z * 256; ldw = 768; }
    else       { Wb = Whh + (z - 3) * 256; ldw = 512; }

    float acc[4][8] = {};
    for (int k0 = 0; k0 < 256; k0 += 16) {
        {
            float4 v = *(const float4*)&arow[k0 + kq];
            As[kq + 0][ms] = v.x; As[kq + 1][ms] = v.y; As[kq + 2][ms] = v.z; As[kq + 3][ms] = v.w;
        }
#pragma unroll
        for (int i = 0; i < 2; i++) {
            int idx = tid * 2 + i;              // 0..511
            int n = idx >> 2, c4 = (idx & 3) * 4;
            float4 v = *(const float4*)&Wb[(size_t)(n0 + n) * ldw + k0 + c4];
            Bs[c4 + 0][n] = v.x; Bs[c4 + 1][n] = v.y; Bs[c4 + 2][n] = v.z; Bs[c4 + 3][n] = v.w;
        }
        __syncthreads();
#pragma unroll
        for (int kk = 0; kk < 16; kk++) {
            float a[4], bv[8];
#pragma unroll
            for (int i = 0; i < 4; i++) a[i] = As[kk][ty * 4 + i];
#pragma unroll
            for (int j = 0; j < 8; j++) bv[j] = Bs[kk][tx * 8 + j];
#pragma unroll
            for (int i = 0; i < 4; i++)
#pragma unroll
                for (int j = 0; j < 8; j++) acc[i][j] += a[i] * bv[j];
        }
        __syncthreads();
    }
    float* gp = g_gpart + (size_t)z * B_ * G_;
#pragma unroll
    for (int i = 0; i < 4; i++)
#pragma unroll
        for (int j = 0; j < 8; j++)
            gp[(ty * 4 + i) * G_ + n0 + tx * 8 + j] = acc[i][j];
}

// ---------------- reduce partials + LSTM cell + store h into H ----------------
__global__ void __launch_bounds__(256) k_lstm(const float* __restrict__ bih,
                                              const float* __restrict__ bhh, int t) {
    int idx = blockIdx.x * 256 + threadIdx.x;
    if (idx >= B_ * D_) return;
    int b = idx >> 9, d = idx & 511;
    float gi = bih[d]        + bhh[d];
    float gf = bih[512 + d]  + bhh[512 + d];
    float gg = bih[1024 + d] + bhh[1024 + d];
    float go = bih[1536 + d] + bhh[1536 + d];
#pragma unroll
    for (int z = 0; z < 5; z++) {
        const float* gp = g_gpart + ((size_t)z * B_ + b) * G_;
        gi += gp[d]; gf += gp[512 + d]; gg += gp[1024 + d]; go += gp[1536 + d];
    }
    float c_old = g_c[idx];
    float cn = (1.f / (1.f + expf(-gf))) * c_old + (1.f / (1.f + expf(-gi))) * tanhf(gg);
    float hn = (1.f / (1.f + expf(-go))) * tanhf(cn);
    g_c[idx] = cn;
    g_h[idx] = hn;
    g_H[(size_t)t * B_ * D_ + idx] = hn;
}

// ---------------- host launcher (kernel launches ONLY) ----------------
extern "C" void kernel_launch(void* const* d_in, const int* in_sizes, int n_in,
                              void* d_out, int out_size) {
    const float* enc   = (const float*)d_in[0];
    const int*   cap   = (const int*)d_in[1];      // int32 captions
    const float* W_enc = (const float*)d_in[2];
    const float* b_enc = (const float*)d_in[3];
    const float* W_dec = (const float*)d_in[4];
    const float* b_dec = (const float*)d_in[5];
    const float* W_full= (const float*)d_in[6];
    // d_in[7] = b_full : softmax shift-invariant, unused
    const float* emb   = (const float*)d_in[8];
    const float* W_ih  = (const float*)d_in[9];
    const float* b_ih  = (const float*)d_in[10];
    const float* W_hh  = (const float*)d_in[11];
    const float* b_hh  = (const float*)d_in[12];
    const float* W_fc  = (const float*)d_in[13];
    const float* b_fc  = (const float*)d_in[14];
    float* out = (float*)d_out;

    k_init<<<128, 256>>>();
    k_transpose<<<dim3(7, 8, 64), dim3(32, 8)>>>(enc);
    // enc_att = feats @ W_enc + b_enc : [12544, 512], K=256
    k_gemm_tf32<0><<<dim3((B_ * P_) / 64, A_ / 64), 128>>>(
        W_enc, b_enc, nullptr, B_ * P_, A_, C_);

    for (int t = 0; t < T_; t++) {
        k_attention<<<64, 256>>>(W_dec, b_dec, W_full);
        k_gates<<<dim3(16, 5), 256>>>(cap, emb, W_ih, W_hh, t);
        k_lstm<<<128, 256>>>(b_ih, b_hh, t);
    }

    // out[b][t][v] = H[t][b][:] @ W_fc + b_fc : M=1280, N=30000, K=512
    k_gemm_tf32<1><<<dim3((T_ * B_) / 64, (V_ + 63) / 64), 128>>>(
        W_fc, b_fc, out, T_ * B_, V_, D_);
}

// round 7
// speedup vs baseline: 1.0472x; 1.0472x over previous
#include <cuda_runtime.h>
#include <mma.h>
#include <cstdint>

using namespace nvcuda;

#define B_ 64
#define C_ 256
#define P_ 196
#define A_ 512
#define D_ 512
#define E_ 512
#define V_ 30000
#define T_ 20
#define G_ 2048   // 4*D

// ---------------- scratch (device globals; no allocation allowed) ----------------
__device__ __align__(128) float g_feats[B_*P_*C_];    // [b][p][c]
__device__ __align__(128) float g_encatt[B_*P_*A_];   // [b][p][a]
__device__ __align__(128) float g_h[B_*D_];
__device__ __align__(128) float g_c[B_*D_];
__device__ __align__(128) float g_decatt[B_*A_];
__device__ __align__(128) float g_logits[B_*224];     // padded 196 -> 224
__device__ __align__(128) float g_ctxp[4*B_*C_];      // context partials [z][b][c]
__device__ __align__(128) float g_gpart[5*B_*G_];     // K-split partial gate sums
__device__ __align__(128) float g_H[T_*B_*D_];        // [t][b][d]

// ---------------- init h0 = c0 = 0 ----------------
__global__ void __launch_bounds__(256) k_init() {
    int i = blockIdx.x * blockDim.x + threadIdx.x;
    if (i < B_ * D_) { g_h[i] = 0.f; g_c[i] = 0.f; }
}

// ---------------- feats[b][p][c] = enc[b][c][p] ----------------
__global__ void __launch_bounds__(256) k_transpose(const float* __restrict__ enc) {
    __shared__ float tile[32][33];
    int b = blockIdx.z, c0 = blockIdx.y * 32, p0 = blockIdx.x * 32;
    int tx = threadIdx.x, ty = threadIdx.y;
#pragma unroll
    for (int i = 0; i < 4; i++) {
        int c = c0 + ty + i * 8, p = p0 + tx;
        if (p < P_) tile[ty + i * 8][tx] = enc[(b * C_ + c) * P_ + p];
    }
    __syncthreads();
#pragma unroll
    for (int i = 0; i < 4; i++) {
        int p = p0 + ty + i * 8, c = c0 + tx;
        if (p < P_) g_feats[(b * P_ + p) * C_ + c] = tile[tx][ty + i * 8];
    }
}

// ---------------- tf32 WMMA GEMM: C[M,N] = A[M,K] @ B[K,N] + bias[N] ----------------
// 64x64 block tile, 4 warps (2x2), each warp 32x32 (2x2 m16n16k8 frags), BK=32.
// MODE 0: A = g_feats, C = g_encatt (enc_att precompute, K=256, N=512)
// MODE 1: A = g_H, C = out with remap row r=t*64+b -> out[(b*T+t)*N+n] (final fc)
template<int MODE>
__global__ void __launch_bounds__(128, 2) k_gemm_tf32(const float* __restrict__ Bm,
                            const float* __restrict__ bias,
                            float* __restrict__ Cout,
                            int M, int N, int K) {
    __shared__ float As[64][40];
    __shared__ float Bs[32][72];
    __shared__ float Cs[64][72];
    const float* Aa = (MODE == 0) ? g_feats : g_H;
    int m0 = blockIdx.x * 64, n0 = blockIdx.y * 64;
    int tid = threadIdx.x;
    int warp = tid >> 5;
    int wm = warp >> 1, wn = warp & 1;

    wmma::fragment<wmma::accumulator, 16, 16, 8, float> acc[2][2];
#pragma unroll
    for (int i = 0; i < 2; i++)
#pragma unroll
        for (int j = 0; j < 2; j++) wmma::fill_fragment(acc[i][j], 0.f);

    for (int k0 = 0; k0 < K; k0 += 32) {
#pragma unroll
        for (int i = 0; i < 4; i++) {           // stage A 64x32
            int idx = tid + i * 128;
            int r = idx >> 3, c4 = (idx & 7) * 4;
            float4 v = *(const float4*)&Aa[(size_t)(m0 + r) * K + k0 + c4];
            *(float4*)&As[r][c4] = v;
        }
#pragma unroll
        for (int i = 0; i < 4; i++) {           // stage B 32x64 (bounds on n)
            int idx = tid + i * 128;
            int kk = idx >> 4, c4 = (idx & 15) * 4;
            int n = n0 + c4;
            float4 v = make_float4(0.f, 0.f, 0.f, 0.f);
            if (n < N) v = *(const float4*)&Bm[(size_t)(k0 + kk) * N + n];
            *(float4*)&Bs[kk][c4] = v;
        }
        __syncthreads();
#pragma unroll
        for (int kk = 0; kk < 32; kk += 8) {
            wmma::fragment<wmma::matrix_a, 16, 16, 8, wmma::precision::tf32, wmma::row_major> a0, a1;
            wmma::fragment<wmma::matrix_b, 16, 16, 8, wmma::precision::tf32, wmma::row_major> b0, b1;
            wmma::load_matrix_sync(a0, &As[wm * 32][kk], 40);
            wmma::load_matrix_sync(a1, &As[wm * 32 + 16][kk], 40);
            wmma::load_matrix_sync(b0, &Bs[kk][wn * 32], 72);
            wmma::load_matrix_sync(b1, &Bs[kk][wn * 32 + 16], 72);
#pragma unroll
            for (int e = 0; e < a0.num_elements; e++) {
                a0.x[e] = wmma::__float_to_tf32(a0.x[e]);
                a1.x[e] = wmma::__float_to_tf32(a1.x[e]);
            }
#pragma unroll
            for (int e = 0; e < b0.num_elements; e++) {
                b0.x[e] = wmma::__float_to_tf32(b0.x[e]);
                b1.x[e] = wmma::__float_to_tf32(b1.x[e]);
            }
            wmma::mma_sync(acc[0][0], a0, b0, acc[0][0]);
            wmma::mma_sync(acc[0][1], a0, b1, acc[0][1]);
            wmma::mma_sync(acc[1][0], a1, b0, acc[1][0]);
            wmma::mma_sync(acc[1][1], a1, b1, acc[1][1]);
        }
        __syncthreads();
    }
#pragma unroll
    for (int i = 0; i < 2; i++)
#pragma unroll
        for (int j = 0; j < 2; j++)
            wmma::store_matrix_sync(&Cs[wm * 32 + i * 16][wn * 32 + j * 16], acc[i][j], 72,
                                    wmma::mem_row_major);
    __syncthreads();
    float* Cdst = (MODE == 0) ? g_encatt : Cout;
    for (int idx = tid; idx < 64 * 64; idx += 128) {
        int rr = idx >> 6, cc = idx & 63;
        int n = n0 + cc;
        if (n >= N) continue;
        int row = m0 + rr;
        float val = Cs[rr][cc] + bias[n];
        if (MODE == 1) {
            int b = row & 63, t = row >> 6;
            Cdst[(size_t)(b * T_ + t) * N + n] = val;
        } else {
            Cdst[(size_t)row * N + n] = val;
        }
    }
}

// ---------------- dec_att[64,512] = h @ W_dec + b_dec (tiled GEMM, 8 blocks) ----------------
__global__ void __launch_bounds__(256) k_decatt(const float* __restrict__ Wd,
                                                const float* __restrict__ bd) {
    __shared__ float As[16][68];   // [k][m]
    __shared__ float Bs[16][68];   // [k][n]
    int n0 = blockIdx.x * 64;
    int tid = threadIdx.x;
    int tx = tid & 15, ty = tid >> 4;
    float acc[4][4] = {};
    for (int k0 = 0; k0 < 512; k0 += 16) {
        {
            int m = tid >> 2, kq = (tid & 3) * 4;
            float4 v = *(const float4*)&g_h[m * 512 + k0 + kq];
            As[kq + 0][m] = v.x; As[kq + 1][m] = v.y; As[kq + 2][m] = v.z; As[kq + 3][m] = v.w;
        }
        {
            int kk = tid >> 4, c4 = (tid & 15) * 4;
            float4 v = *(const float4*)&Wd[(k0 + kk) * 512 + n0 + c4];
            *(float4*)&Bs[kk][c4] = v;
        }
        __syncthreads();
#pragma unroll
        for (int kk = 0; kk < 16; kk++) {
            float a[4], b[4];
#pragma unroll
            for (int i = 0; i < 4; i++) a[i] = As[kk][ty * 4 + i];
#pragma unroll
            for (int j = 0; j < 4; j++) b[j] = Bs[kk][tx * 4 + j];
#pragma unroll
            for (int i = 0; i < 4; i++)
#pragma unroll
                for (int j = 0; j < 4; j++) acc[i][j] += a[i] * b[j];
        }
        __syncthreads();
    }
#pragma unroll
    for (int i = 0; i < 4; i++)
#pragma unroll
        for (int j = 0; j < 4; j++) {
            int m = ty * 4 + i, n = tx * 4 + j;
            g_decatt[m * 512 + n0 + n] = acc[i][j] + bd[n0 + n];
        }
}

// ---------------- logits[b][p] = sum_k relu(encatt[b][p][k] + dec[k]) * Wf[k] ----------------
// grid (64, 25): one warp per p, 8 p per block -> 1600 blocks
__global__ void __launch_bounds__(256) k_logits(const float* __restrict__ Wf) {
    int b = blockIdx.x;
    int tid = threadIdx.x, lane = tid & 31, warp = tid >> 5;
    __shared__ float sdec[512], swf[512];
    for (int i = tid; i < 512; i += 256) { sdec[i] = g_decatt[b * 512 + i]; swf[i] = Wf[i]; }
    __syncthreads();
    int p = blockIdx.y * 8 + warp;
    if (p >= P_) return;
    const float* row = &g_encatt[((size_t)b * P_ + p) * A_];
    float acc = 0.f;
#pragma unroll
    for (int j = 0; j < 4; j++) {
        int k = (lane + j * 32) * 4;
        float4 e = *(const float4*)&row[k];
        float4 dd = *(const float4*)&sdec[k];
        float4 w = *(const float4*)&swf[k];
        acc += fmaxf(e.x + dd.x, 0.f) * w.x + fmaxf(e.y + dd.y, 0.f) * w.y
             + fmaxf(e.z + dd.z, 0.f) * w.z + fmaxf(e.w + dd.w, 0.f) * w.w;
    }
#pragma unroll
    for (int o = 16; o > 0; o >>= 1) acc += __shfl_down_sync(0xffffffff, acc, o);
    if (lane == 0) g_logits[b * 224 + p] = acc;
}

// ---------------- softmax (redundant per z) + context partial over 49-p chunk ----------------
// grid (64, 4): block (b, z) writes g_ctxp[z][b][c] for its p-range
__global__ void __launch_bounds__(256) k_softctx() {
    int b = blockIdx.x, z = blockIdx.y;
    int tid = threadIdx.x, lane = tid & 31, warp = tid >> 5;
    __shared__ float slog[224], sred[8];
    float lg = (tid < P_) ? g_logits[b * 224 + tid] : -1e30f;
    slog[tid < 224 ? tid : 0] = 0.f;  // pre-barrier init; lanes>=224 alias slog[0], rewritten below
    // max
    float m = lg;
#pragma unroll
    for (int o = 16; o > 0; o >>= 1) m = fmaxf(m, __shfl_xor_sync(0xffffffff, m, o));
    if (lane == 0) sred[warp] = m;
    __syncthreads();
    float gm = fmaxf(fmaxf(fmaxf(sred[0], sred[1]), fmaxf(sred[2], sred[3])),
                     fmaxf(fmaxf(sred[4], sred[5]), fmaxf(sred[6], sred[7])));
    __syncthreads();
    // exp + sum
    float e = (tid < P_) ? expf(lg - gm) : 0.f;
    if (tid < P_) slog[tid] = e;
    float s = e;
#pragma unroll
    for (int o = 16; o > 0; o >>= 1) s += __shfl_xor_sync(0xffffffff, s, o);
    if (lane == 0) sred[warp] = s;
    __syncthreads();
    float tot = sred[0] + sred[1] + sred[2] + sred[3] + sred[4] + sred[5] + sred[6] + sred[7];
    float inv = 1.f / tot;
    __syncthreads();
    // context partial: p in [z*49, z*49+49), thread = c (coalesced)
    const float* fb = &g_feats[(size_t)b * P_ * C_];
    int p0 = z * 49;
    float accv = 0.f;
#pragma unroll 7
    for (int i = 0; i < 49; i++) {
        int p = p0 + i;
        accv += slog[p] * fb[p * C_ + tid];
    }
    g_ctxp[((size_t)z * B_ + b) * C_ + tid] = accv * inv;
}

// ---------------- gates partial GEMM: K split into 5 chunks of 256 ----------------
// x~[b][k] = [ emb(512) | ctx(256) | h(512) ],  W~[n][k] = [ W_ih(768) | W_hh(512) ]
__global__ void __launch_bounds__(256) k_gates(const int* __restrict__ cap,
                        const float* __restrict__ emb,
                        const float* __restrict__ Wih,
                        const float* __restrict__ Whh,
                        int t) {
    __shared__ float As[16][68];    // [k][m]
    __shared__ float Bs[16][132];   // [k][n]
    int n0 = blockIdx.x * 128;
    int z = blockIdx.y;             // K chunk 0..4
    int tid = threadIdx.x;
    int tx = tid & 15, ty = tid >> 4;

    int ms = tid >> 2, kq = (tid & 3) * 4;
    const float* arow = nullptr;
    if (z < 2) { int ci = cap[ms * T_ + t]; arow = emb + (size_t)ci * E_ + z * 256; }
    else if (z > 2) arow = g_h + ms * D_ + (z - 3) * 256;
    const float* Wb; int ldw;
    if (z < 3) { Wb = Wih + z * 256; ldw = 768; }
    else       { Wb = Whh + (z - 3) * 256; ldw = 512; }

    float acc[4][8] = {};
    for (int k0 = 0; k0 < 256; k0 += 16) {
        {
            float4 v;
            if (z == 2) {   // ctx = sum of 4 partials
                float4 v0 = *(const float4*)&g_ctxp[((size_t)0 * B_ + ms) * C_ + k0 + kq];
                float4 v1 = *(const float4*)&g_ctxp[((size_t)1 * B_ + ms) * C_ + k0 + kq];
                float4 v2 = *(const float4*)&g_ctxp[((size_t)2 * B_ + ms) * C_ + k0 + kq];
                float4 v3 = *(const float4*)&g_ctxp[((size_t)3 * B_ + ms) * C_ + k0 + kq];
                v = make_float4(v0.x + v1.x + v2.x + v3.x, v0.y + v1.y + v2.y + v3.y,
                                v0.z + v1.z + v2.z + v3.z, v0.w + v1.w + v2.w + v3.w);
            } else {
                v = *(const float4*)&arow[k0 + kq];
            }
            As[kq + 0][ms] = v.x; As[kq + 1][ms] = v.y; As[kq + 2][ms] = v.z; As[kq + 3][ms] = v.w;
        }
#pragma unroll
        for (int i = 0; i < 2; i++) {
            int idx = tid * 2 + i;              // 0..511
            int n = idx >> 2, c4 = (idx & 3) * 4;
            float4 v = *(const float4*)&Wb[(size_t)(n0 + n) * ldw + k0 + c4];
            Bs[c4 + 0][n] = v.x; Bs[c4 + 1][n] = v.y; Bs[c4 + 2][n] = v.z; Bs[c4 + 3][n] = v.w;
        }
        __syncthreads();
#pragma unroll
        for (int kk = 0; kk < 16; kk++) {
            float a[4], bv[8];
#pragma unroll
            for (int i = 0; i < 4; i++) a[i] = As[kk][ty * 4 + i];
#pragma unroll
            for (int j = 0; j < 8; j++) bv[j] = Bs[kk][tx * 8 + j];
#pragma unroll
            for (int i = 0; i < 4; i++)
#pragma unroll
                for (int j = 0; j < 8; j++) acc[i][j] += a[i] * bv[j];
        }
        __syncthreads();
    }
    float* gp = g_gpart + (size_t)z * B_ * G_;
#pragma unroll
    for (int i = 0; i < 4; i++)
#pragma unroll
        for (int j = 0; j < 8; j++)
            gp[(ty * 4 + i) * G_ + n0 + tx * 8 + j] = acc[i][j];
}

// ---------------- reduce partials + LSTM cell + store h into H ----------------
__global__ void __launch_bounds__(256) k_lstm(const float* __restrict__ bih,
                                              const float* __restrict__ bhh, int t) {
    int idx = blockIdx.x * 256 + threadIdx.x;
    if (idx >= B_ * D_) return;
    int b = idx >> 9, d = idx & 511;
    float gi = bih[d]        + bhh[d];
    float gf = bih[512 + d]  + bhh[512 + d];
    float gg = bih[1024 + d] + bhh[1024 + d];
    float go = bih[1536 + d] + bhh[1536 + d];
#pragma unroll
    for (int z = 0; z < 5; z++) {
        const float* gp = g_gpart + ((size_t)z * B_ + b) * G_;
        gi += gp[d]; gf += gp[512 + d]; gg += gp[1024 + d]; go += gp[1536 + d];
    }
    float c_old = g_c[idx];
    float cn = (1.f / (1.f + expf(-gf))) * c_old + (1.f / (1.f + expf(-gi))) * tanhf(gg);
    float hn = (1.f / (1.f + expf(-go))) * tanhf(cn);
    g_c[idx] = cn;
    g_h[idx] = hn;
    g_H[(size_t)t * B_ * D_ + idx] = hn;
}

// ---------------- host launcher (kernel launches ONLY) ----------------
extern "C" void kernel_launch(void* const* d_in, const int* in_sizes, int n_in,
                              void* d_out, int out_size) {
    const float* enc   = (const float*)d_in[0];
    const int*   cap   = (const int*)d_in[1];      // int32 captions
    const float* W_enc = (const float*)d_in[2];
    const float* b_enc = (const float*)d_in[3];
    const float* W_dec = (const float*)d_in[4];
    const float* b_dec = (const float*)d_in[5];
    const float* W_full= (const float*)d_in[6];
    // d_in[7] = b_full : softmax shift-invariant, unused
    const float* emb   = (const float*)d_in[8];
    const float* W_ih  = (const float*)d_in[9];
    const float* b_ih  = (const float*)d_in[10];
    const float* W_hh  = (const float*)d_in[11];
    const float* b_hh  = (const float*)d_in[12];
    const float* W_fc  = (const float*)d_in[13];
    const float* b_fc  = (const float*)d_in[14];
    float* out = (float*)d_out;

    k_init<<<128, 256>>>();
    k_transpose<<<dim3(7, 8, 64), dim3(32, 8)>>>(enc);
    // enc_att = feats @ W_enc + b_enc : [12544, 512], K=256
    k_gemm_tf32<0><<<dim3((B_ * P_) / 64, A_ / 64), 128>>>(
        W_enc, b_enc, nullptr, B_ * P_, A_, C_);

    for (int t = 0; t < T_; t++) {
        k_decatt<<<8, 256>>>(W_dec, b_dec);
        k_logits<<<dim3(64, 25), 256>>>(W_full);
        k_softctx<<<dim3(64, 4), 256>>>();
        k_gates<<<dim3(16, 5), 256>>>(cap, emb, W_ih, W_hh, t);
        k_lstm<<<128, 256>>>(b_ih, b_hh, t);
    }

    // out[b][t][v] = H[t][b][:] @ W_fc + b_fc : M=1280, N=30000, K=512
    k_gemm_tf32<1><<<dim3((T_ * B_) / 64, (V_ + 63) / 64), 128>>>(
        W_fc, b_fc, out, T_ * B_, V_, D_);
}